// round 13
// baseline (speedup 1.0000x reference)
#include <cuda_runtime.h>
#include <math.h>
#include <stdint.h>

#define E_N     100000
#define NODES   10000
#define DIMIN   72
#define NR      1216
#define HID     100
#define NY      25
#define NT_TAB  513            // radial table nodes over [0.7, 3.2], h = 2.5/512
#define CH      16             // edges per msg3 block (4 warps x 4 edges)
#define MAXCH   32             // chunks per bucket (capacity 512 edges; max bucket ~490)

// ---------------- scratch (device globals; zero-init) ----------------
__device__ float    g_T [(size_t)NT_TAB * NR];   // radial table f(d_j)
__device__ float    g_Yb[(size_t)E_N * NY];
__device__ float    g_CG[1225];
__device__ float    g_K [25];
__device__ uint32_t g_planTY[259];
__device__ uint32_t g_planG [552];
__device__ int      g_cnt[512];
__device__ int      g_off[513];
__device__ int      g_cur[512];
__device__ int      g_perm[E_N];
__device__ int      g_done;

// ---------------- triple metadata (19 (lo,li,l) triples) ----------------
__constant__ int TRIP_LO[19]   = {0,0,0, 1,1,1,1,1,1,1, 2,2,2,2,2,2,2,2,2};
__constant__ int TRIP_LI[19]   = {0,1,2, 0,1,1,1,2,2,2, 0,1,1,1,2,2,2,2,2};
__constant__ int TRIP_L [19]   = {0,1,2, 1,0,1,2,1,2,3, 2,1,2,3,0,1,2,3,4};
__constant__ int TRIP_CGO[19]  = {0,1,10, 35,44,53,80,125,170,245, 350,375,420,495,600,625,700,825,1000};
__constant__ int TRIP_RB[19]   = {0,64,128, 192,256,256,256,448,448,448, 640,704,704,704,896,896,896,896,896};
__constant__ int TRIP_FB[19]   = {0,8,32, 0,8,8,8,32,32,32, 0,8,8,8,32,32,32,32,32};
__constant__ int TRIP_KK[19]   = {0,0,0, 0,0,1,2,0,1,2, 0,0,1,2,0,1,2,3,4};
__constant__ int TRIP_NL[19]   = {1,1,1, 1,3,3,3,3,3,3, 1,3,3,3,5,5,5,5,5};
__constant__ int TRIP_NP[19]   = {1,1,1, 3,3,3,3,3,3,3, 5,5,5,5,5,5,5,5,5};
__constant__ int TRIP_NQ[19]   = {1,3,5, 1,3,3,3,5,5,5, 1,3,3,3,5,5,5,5,5};
__constant__ int TY_OFF[20] = {0,1,4,9, 12,21,30,39,54,69, 84,89,104,119,134,159,184,209,234, 259};
__constant__ int G_OFF [20] = {0,8,16, 24,48,72,96,120,144,168, 192,232,272,312,352,392,432,472,512, 552};
__constant__ int TSTART[4] = {0, 3, 10, 19};

__device__ __forceinline__ int bucket_of(float d) {
    float u = (d - 0.7f) * ((float)(NT_TAB - 1) / 2.5f);
    return min(max((int)floorf(u), 1), 510);
}

// ---------------- CG math (doubles) ----------------
__device__ __forceinline__ double dfact(int n) {
    const double f[11] = {1.,1.,2.,6.,24.,120.,720.,5040.,40320.,362880.,3628800.};
    return f[n];
}
__device__ double w3j(int j1,int j2,int j3,int m1,int m2,int m3) {
    if (m1 + m2 + m3 != 0) return 0.0;
    if (j3 < abs(j1 - j2) || j3 > j1 + j2) return 0.0;
    if (abs(m1) > j1 || abs(m2) > j2 || abs(m3) > j3) return 0.0;
    double pre = sqrt(dfact(j1+j2-j3)*dfact(j1-j2+j3)*dfact(-j1+j2+j3)/dfact(j1+j2+j3+1)
                 *dfact(j1+m1)*dfact(j1-m1)*dfact(j2+m2)*dfact(j2-m2)*dfact(j3+m3)*dfact(j3-m3));
    int kmin = max(0, max(j2 - j3 - m1, j1 - j3 + m2));
    int kmax = min(j1 + j2 - j3, min(j1 - m1, j2 + m2));
    double s = 0.0;
    for (int k = kmin; k <= kmax; ++k) {
        double den = dfact(k)*dfact(j1+j2-j3-k)*dfact(j1-m1-k)*dfact(j2+m2-k)
                    *dfact(j3-j2+m1+k)*dfact(j3-j1-m2+k);
        s += ((k & 1) ? -1.0 : 1.0) / den;
    }
    int ph = j1 - j2 - m3;
    return ((ph & 1) ? -1.0 : 1.0) * pre * s;
}
__device__ __forceinline__ double2 Uent(int l, int a, int mc) {
    const double is2 = 0.70710678118654752440;
    int mr = a - l, m = mc - l;
    double2 z; z.x = 0.0; z.y = 0.0;
    if (mr == 0) { if (m == 0) z.x = 1.0; }
    else if (mr > 0) {
        if (m == mr)       z.x = ((mr & 1) ? -1.0 : 1.0) * is2;
        else if (m == -mr) z.x = is2;
    } else {
        int ma = -mr;
        if (m == mr)      z.y = is2;
        else if (m == ma) z.y = -((ma & 1) ? -1.0 : 1.0) * is2;
    }
    return z;
}
__device__ __forceinline__ double2 cmul(double2 a, double2 b) {
    double2 r; r.x = a.x*b.x - a.y*b.y; r.y = a.x*b.y + a.y*b.x; return r;
}

// warp-per-entry CG init; block 0 also fills K norms, plan tables, and resets sort state
__global__ void cg_init_kernel() {
    int gw = (blockIdx.x * blockDim.x + threadIdx.x) >> 5;
    int lane = threadIdx.x & 31;

    if (blockIdx.x == 0) {
        if (threadIdx.x == 0) g_done = 0;
        for (int t = threadIdx.x; t < 512; t += 256) g_cnt[t] = 0;
        for (int t = threadIdx.x; t < 25 + 259 + 552; t += 256) {
            if (t < 25) {
                int c = t;
                int l = 0;
                while ((l+1)*(l+1) <= c) l++;
                int m = c - l*l - l;
                int am = abs(m);
                double K = sqrt((2.0*l + 1.0) / (4.0 * 3.14159265358979323846) * dfact(l - am) / dfact(l + am));
                g_K[c] = (float)(m == 0 ? K : sqrt(2.0) * K);
            } else if (t < 25 + 259) {
                int item = t - 25;
                int tr = 0;
                while (item >= TY_OFF[tr + 1]) ++tr;
                int local = item - TY_OFF[tr];
                int np = TRIP_NP[tr], nq = TRIP_NQ[tr];
                int q = local / np, p = local % np;
                int l = TRIP_L[tr], nr2 = 2 * l + 1;
                uint32_t cgbase = (uint32_t)(TRIP_CGO[tr] + (p * nq + q) * nr2);
                g_planTY[item] = cgbase | ((uint32_t)(l * l) << 12) | ((uint32_t)nr2 << 17);
            } else {
                int item = t - 25 - 259;
                int tr = 0;
                while (item >= G_OFF[tr + 1]) ++tr;
                int local = item - G_OFF[tr];
                int np = TRIP_NP[tr], nq = TRIP_NQ[tr];
                int v = local / np, p = local % np;
                uint32_t fbase = (uint32_t)(TRIP_FB[tr] + v * nq);
                uint32_t tyb   = (uint32_t)(TY_OFF[tr] + p);
                g_planG[item] = fbase | ((uint32_t)nq << 7) | (tyb << 10) | ((uint32_t)np << 19);
            }
        }
    }

    if (gw >= 1225) return;
    int idx = gw;
    int t = 0;
    for (t = 0; t < 19; ++t) {
        int sz = (2*TRIP_LO[t]+1) * (2*TRIP_LI[t]+1) * (2*TRIP_L[t]+1);
        if (idx < TRIP_CGO[t] + sz) break;
    }
    int lo = TRIP_LO[t], li = TRIP_LI[t], l = TRIP_L[t];
    int local = idx - TRIP_CGO[t];
    int nq = 2*li + 1, nr = 2*l + 1;
    int p = local / (nq * nr);
    int q = (local / nr) % nq;
    int r = local % nr;
    int n1 = 2*lo + 1;
    int total = n1 * nq * nr;
    double s = 0.0;
    for (int it = lane; it < total; it += 32) {
        int m  = it / (nq * nr);
        int rem = it % (nq * nr);
        int n  = rem / nr;
        int pp = rem % nr;
        double2 u1 = Uent(lo, p, m);
        if (u1.x == 0.0 && u1.y == 0.0) continue;
        double2 u2 = Uent(li, q, n);
        if (u2.x == 0.0 && u2.y == 0.0) continue;
        double2 u3 = Uent(l, r, pp);
        if (u3.x == 0.0 && u3.y == 0.0) continue;
        double w = w3j(lo, li, l, m - lo, n - li, pp - l);
        if (w == 0.0) continue;
        double2 u = cmul(cmul(u1, u2), u3);
        s += (u.x + u.y) * w;
    }
#pragma unroll
    for (int off = 16; off > 0; off >>= 1)
        s += __shfl_down_sync(0xffffffffu, s, off);
    if (lane == 0) g_CG[idx] = (float)s;
}

// ---------------- prep: SH (warp/edge) + zero out + distance histogram + last-block prefix ----------------
__global__ __launch_bounds__(256)
void prep_kernel(const float* __restrict__ rel, const float* __restrict__ dist,
                 float* __restrict__ out, int outN) {
    int e = blockIdx.x * 8 + (threadIdx.x >> 5);
    int lane = threadIdx.x & 31;
    int gid = blockIdx.x * 256 + threadIdx.x;
    if (gid < outN) out[gid] = 0.0f;

    if (e < E_N) {
        if (lane == 0) atomicAdd(&g_cnt[bucket_of(dist[e])], 1);
        if (lane < 25) {
            float vx = rel[e*3+0], vy = rel[e*3+1], vz = rel[e*3+2];
            float r = sqrtf(vx*vx + vy*vy + vz*vz);
            float inv = 1.0f / fmaxf(r, 1e-9f);
            float x = vx * inv, y = vy * inv, z = vz * inv;

            float A[5], B[5];
            A[0] = 1.0f; B[0] = 0.0f;
#pragma unroll
            for (int m = 1; m <= 4; ++m) {
                A[m] = x * A[m-1] - y * B[m-1];
                B[m] = x * B[m-1] + y * A[m-1];
            }
            float p[5][5];
            p[0][0] = 1.0f;
#pragma unroll
            for (int m = 0; m <= 4; ++m) {
                if (m > 0) p[m][m] = -(2.0f * m - 1.0f) * p[m-1][m-1];
                if (m + 1 <= 4) p[m+1][m] = (2.0f * m + 1.0f) * z * p[m][m];
#pragma unroll
                for (int l = m + 2; l <= 4; ++l)
                    p[l][m] = ((2.0f*l - 1.0f) * z * p[l-1][m] - (l + m - 1.0f) * p[l-2][m]) / (float)(l - m);
            }
            float val = 0.0f;
            int c = 0;
#pragma unroll
            for (int l = 0; l <= 4; ++l) {
#pragma unroll
                for (int m = -4; m <= 4; ++m) {
                    if (m < -l || m > l) continue;
                    int am = m < 0 ? -m : m;
                    if (c == lane) {
                        float gk = g_K[c];
                        if (m == 0)      val = gk * p[l][0];
                        else if (m > 0)  val = gk * p[l][am] * A[am];
                        else             val = gk * p[l][am] * B[am];
                    }
                    c++;
                }
            }
            g_Yb[(size_t)e * NY + lane] = val;
        }
    }

    // last block performs bucket prefix scan
    __syncthreads();
    __threadfence();
    __shared__ int ticket;
    if (threadIdx.x == 0) ticket = atomicAdd(&g_done, 1);
    __syncthreads();
    if (ticket == gridDim.x - 1 && threadIdx.x < 32) {
        int l = threadIdx.x;
        int loc[16];
        int sum = 0;
#pragma unroll
        for (int k = 0; k < 16; ++k) { int v = __ldcg(&g_cnt[l * 16 + k]); loc[k] = v; sum += v; }
        int incl = sum;
#pragma unroll
        for (int off = 1; off < 32; off <<= 1) {
            int n = __shfl_up_sync(0xffffffffu, incl, off);
            if (l >= off) incl += n;
        }
        int run = incl - sum;
#pragma unroll
        for (int k = 0; k < 16; ++k) {
            g_off[l * 16 + k] = run;
            g_cur[l * 16 + k] = run;
            run += loc[k];
        }
        if (l == 31) g_off[512] = run;
    }
}

// ---------------- fused: radial table build (blocks < NT_TAB) + edge scatter ----------------
__global__ __launch_bounds__(256)
void table_scatter_kernel(const float* __restrict__ W0, const float* __restrict__ W1,
                          const float* __restrict__ W2, const float* __restrict__ W3,
                          const float* __restrict__ dist) {
    __shared__ float ha[HID], hbuf[HID], hb[10];
    if (blockIdx.x < NT_TAB) {
        const int node = blockIdx.x;
        const int t = threadIdx.x;
        const float d = 0.7f + 2.5f * (float)node / (float)(NT_TAB - 1);

        if (t < 10) {
            float c = 0.7f + (2.5f / 9.0f) * (float)t;
            float tt = (d - c) * 4.5f;
            hb[t] = expf(-tt * tt) * (1.0f / 1.423085244900308f);
        }
        __syncthreads();
        if (t < HID) {
            float s = 0.0f;
#pragma unroll
            for (int b = 0; b < 10; ++b) s += hb[b] * W0[b * HID + t];
            s *= 0.31622776601683794f;
            ha[t] = s / (1.0f + expf(-s));
        }
        __syncthreads();
        if (t < HID) {
            float s = 0.0f;
            for (int k = 0; k < HID; ++k) s += ha[k] * W1[k * HID + t];
            s *= 0.1f;
            hbuf[t] = s / (1.0f + expf(-s));
        }
        __syncthreads();
        if (t < HID) {
            float s = 0.0f;
            for (int k = 0; k < HID; ++k) s += hbuf[k] * W2[k * HID + t];
            s *= 0.1f;
            ha[t] = s / (1.0f + expf(-s));
        }
        __syncthreads();
        for (int o = t; o < NR; o += 256) {
            float s = 0.0f;
            for (int k = 0; k < HID; ++k) s += ha[k] * W3[(size_t)k * NR + o];
            g_T[(size_t)node * NR + o] = 0.1f * s;
        }
    } else {
        int i = (blockIdx.x - NT_TAB) * 256 + threadIdx.x;
        if (i < E_N) {
            int b = bucket_of(dist[i]);
            int pos = atomicAdd(&g_cur[b], 1);
            g_perm[pos] = i;
        }
    }
}

// ---------------- msg3: warp-per-edge on bucketed edges; barriers only per warp ----------------
// dynamic smem layout (floats):
//   Ts   [4*NR]            staged table rows
//   Rw   [4][NR]           per-warp interpolated R
//   tYw  [4][260]
//   Gw   [4][552]
//   Fw   [4][72]
//   Yw   [4][28]
#define SM_TS   0
#define SM_RW   (4 * NR)
#define SM_TY   (SM_RW + 4 * NR)
#define SM_G    (SM_TY + 4 * 260)
#define SM_F    (SM_G + 4 * 552)
#define SM_Y    (SM_F + 4 * 72)
#define SM_MSG_TOT ((SM_Y + 4 * 28) * 4)        // bytes

__global__ __launch_bounds__(128)
void msg3_kernel(const int* __restrict__ ei, const float* __restrict__ x,
                 const float* __restrict__ dist, float* __restrict__ out) {
    extern __shared__ float sm[];
    const int b = blockIdx.x;          // bucket (1..510 populated; 0,511 empty)
    const int t = threadIdx.x;
    const int w = t >> 5;
    const int lane = t & 31;

    const int s0 = g_off[b] + blockIdx.y * CH;
    const int s1 = min(g_off[b + 1], s0 + CH);
    if (s0 >= s1) return;
    const int ne = s1 - s0;

    // stage the 4 table rows (rows b-1 .. b+2)
    {
        const float4* __restrict__ Tsrc = (const float4*)(g_T + (size_t)(b - 1) * NR);
        float4* Td = (float4*)(sm + SM_TS);
        for (int i = t; i < NR; i += 128) Td[i] = __ldg(Tsrc + i);
    }
    __syncthreads();

    float* Rw  = sm + SM_RW + w * NR;
    float* tYw = sm + SM_TY + w * 260;
    float* Gw  = sm + SM_G  + w * 552;
    float* Fw  = sm + SM_F  + w * 72;
    float* Yw  = sm + SM_Y  + w * 28;
    const float* Ts = sm + SM_TS;

    for (int j = w; j < ne; j += 4) {
        const int e   = g_perm[s0 + j];
        const int src = ei[e];
        const int dst = ei[E_N + e];
        float u = (dist[e] - 0.7f) * ((float)(NT_TAB - 1) / 2.5f);
        float tt = u - (float)b;
        float tm = tt - 1.0f, tp = tt + 1.0f, tm2 = tt - 2.0f;
        const float w0 = -tt * tm * tm2 * (1.0f / 6.0f);
        const float w1 =  tp * tm * tm2 * 0.5f;
        const float w2 = -tp * tt * tm2 * 0.5f;
        const float w3 =  tp * tt * tm  * (1.0f / 6.0f);

        // load F, Y for this edge (warp-coalesced)
        for (int k = lane; k < DIMIN; k += 32) Fw[k] = x[(size_t)src * DIMIN + k];
        if (lane < NY) Yw[lane] = g_Yb[(size_t)e * NY + lane];

        // interp R from staged rows
#pragma unroll 5
        for (int i = lane; i < NR; i += 32)
            Rw[i] = w0 * Ts[i] + w1 * Ts[NR + i] + w2 * Ts[2 * NR + i] + w3 * Ts[3 * NR + i];
        __syncwarp();

        // pass 1: tY
        for (int item = lane; item < 259; item += 32) {
            uint32_t plan = __ldg(&g_planTY[item]);
            int cg  = plan & 0xFFF;
            int yb  = (plan >> 12) & 31;
            int nr2 = plan >> 17;
            float s = 0.0f;
            for (int r = 0; r < nr2; ++r)
                s += __ldg(&g_CG[cg + r]) * Yw[yb + r];
            tYw[item] = s;
        }
        __syncwarp();

        // pass 2: G
        for (int item = lane; item < 552; item += 32) {
            uint32_t plan = __ldg(&g_planG[item]);
            int fb  = plan & 127;
            int nq  = (plan >> 7) & 7;
            int tyb = (plan >> 10) & 511;
            int np  = (plan >> 19) & 7;
            float s = 0.0f;
            for (int q = 0; q < nq; ++q)
                s += Fw[fb + q] * tYw[tyb + q * np];
            Gw[item] = s;
        }
        __syncwarp();

        // pass 3: contract with R, scatter (72 outputs over 32 lanes)
        for (int o = lane; o < DIMIN; o += 32) {
            int i, uu, p, np;
            if (o < 8)       { i = 0; uu = o;            p = 0;            np = 1; }
            else if (o < 32) { i = 1; uu = (o - 8) / 3;  p = (o - 8) % 3;  np = 3; }
            else             { i = 2; uu = (o - 32) / 5; p = (o - 32) % 5; np = 5; }
            float acc = 0.0f;
            for (int tr = TSTART[i]; tr < TSTART[i + 1]; ++tr) {
                int nl = TRIP_NL[tr], kk = TRIP_KK[tr];
                int rb = TRIP_RB[tr] + uu * 8 * nl + kk;
                int gb = G_OFF[tr] + p;
                float s = 0.0f;
#pragma unroll
                for (int v = 0; v < 8; ++v)
                    s += Rw[rb + v * nl] * Gw[gb + v * np];
                acc += s;
            }
            const float nse[3] = {24.0f, 56.0f, 72.0f};
            float normi = 3.5449077018110318f * sqrtf(2.0f * i + 1.0f) * rsqrtf(nse[i]);
            atomicAdd(&out[(size_t)dst * DIMIN + o], acc * normi);
        }
        __syncwarp();
    }
}

// ---------------- launch ----------------
extern "C" void kernel_launch(void* const* d_in, const int* in_sizes, int n_in,
                              void* d_out, int out_size) {
    const int*   ei   = (const int*)  d_in[0];
    const float* x    = (const float*)d_in[1];
    const float* dist = (const float*)d_in[2];
    const float* rel  = (const float*)d_in[3];
    const float* W0   = (const float*)d_in[4];
    const float* W1   = (const float*)d_in[5];
    const float* W2   = (const float*)d_in[6];
    const float* W3   = (const float*)d_in[7];
    float* out = (float*)d_out;

    const int scatter_blocks = (E_N + 255) / 256;   // 391

    cudaFuncSetAttribute(msg3_kernel, cudaFuncAttributeMaxDynamicSharedMemorySize, SM_MSG_TOT);

    cg_init_kernel<<<154, 256>>>();                                        // 0
    prep_kernel<<<(E_N + 7) / 8, 256>>>(rel, dist, out, out_size);         // 1
    table_scatter_kernel<<<NT_TAB + scatter_blocks, 256>>>(W0, W1, W2, W3, dist); // 2
    msg3_kernel<<<dim3(512, MAXCH), 128, SM_MSG_TOT>>>(ei, x, dist, out);  // 3 <- ncu
}

// round 15
// speedup vs baseline: 1.9034x; 1.9034x over previous
#include <cuda_runtime.h>
#include <math.h>
#include <stdint.h>

#define E_N     100000
#define NODES   10000
#define DIMIN   72
#define NR      1216
#define HID     100
#define NY      25
#define NT_TAB  513            // radial table nodes over [0.7, 3.2], h = 2.5/512

// ---------------- scratch (device globals; zero-init) ----------------
__device__ float    g_T [(size_t)NT_TAB * NR];   // radial table f(d_j)
__device__ float    g_Yb[(size_t)E_N * NY];
__device__ float    g_CG[1225];
__device__ float    g_K [25];
__device__ uint32_t g_planTY[259];
__device__ uint32_t g_planG [552];
__device__ uint32_t g_planP [552];

// ---------------- triple metadata (19 (lo,li,l) triples) ----------------
__constant__ int TRIP_LO[19]   = {0,0,0, 1,1,1,1,1,1,1, 2,2,2,2,2,2,2,2,2};
__constant__ int TRIP_LI[19]   = {0,1,2, 0,1,1,1,2,2,2, 0,1,1,1,2,2,2,2,2};
__constant__ int TRIP_L [19]   = {0,1,2, 1,0,1,2,1,2,3, 2,1,2,3,0,1,2,3,4};
__constant__ int TRIP_CGO[19]  = {0,1,10, 35,44,53,80,125,170,245, 350,375,420,495,600,625,700,825,1000};
__constant__ int TRIP_RB[19]   = {0,64,128, 192,256,256,256,448,448,448, 640,704,704,704,896,896,896,896,896};
__constant__ int TRIP_FB[19]   = {0,8,32, 0,8,8,8,32,32,32, 0,8,8,8,32,32,32,32,32};
__constant__ int TRIP_KK[19]   = {0,0,0, 0,0,1,2,0,1,2, 0,0,1,2,0,1,2,3,4};
__constant__ int TRIP_NL[19]   = {1,1,1, 1,3,3,3,3,3,3, 1,3,3,3,5,5,5,5,5};
__constant__ int TRIP_NP[19]   = {1,1,1, 3,3,3,3,3,3,3, 5,5,5,5,5,5,5,5,5};
__constant__ int TRIP_NQ[19]   = {1,3,5, 1,3,3,3,5,5,5, 1,3,3,3,5,5,5,5,5};
__constant__ int TY_OFF[20] = {0,1,4,9, 12,21,30,39,54,69, 84,89,104,119,134,159,184,209,234, 259};
__constant__ int G_OFF [20] = {0,8,16, 24,48,72,96,120,144,168, 192,232,272,312,352,392,432,472,512, 552};

// ---------------- CG math (doubles) ----------------
__device__ __forceinline__ double dfact(int n) {
    const double f[11] = {1.,1.,2.,6.,24.,120.,720.,5040.,40320.,362880.,3628800.};
    return f[n];
}
__device__ double w3j(int j1,int j2,int j3,int m1,int m2,int m3) {
    if (m1 + m2 + m3 != 0) return 0.0;
    if (j3 < abs(j1 - j2) || j3 > j1 + j2) return 0.0;
    if (abs(m1) > j1 || abs(m2) > j2 || abs(m3) > j3) return 0.0;
    double pre = sqrt(dfact(j1+j2-j3)*dfact(j1-j2+j3)*dfact(-j1+j2+j3)/dfact(j1+j2+j3+1)
                 *dfact(j1+m1)*dfact(j1-m1)*dfact(j2+m2)*dfact(j2-m2)*dfact(j3+m3)*dfact(j3-m3));
    int kmin = max(0, max(j2 - j3 - m1, j1 - j3 + m2));
    int kmax = min(j1 + j2 - j3, min(j1 - m1, j2 + m2));
    double s = 0.0;
    for (int k = kmin; k <= kmax; ++k) {
        double den = dfact(k)*dfact(j1+j2-j3-k)*dfact(j1-m1-k)*dfact(j2+m2-k)
                    *dfact(j3-j2+m1+k)*dfact(j3-j1-m2+k);
        s += ((k & 1) ? -1.0 : 1.0) / den;
    }
    int ph = j1 - j2 - m3;
    return ((ph & 1) ? -1.0 : 1.0) * pre * s;
}
__device__ __forceinline__ double2 Uent(int l, int a, int mc) {
    const double is2 = 0.70710678118654752440;
    int mr = a - l, m = mc - l;
    double2 z; z.x = 0.0; z.y = 0.0;
    if (mr == 0) { if (m == 0) z.x = 1.0; }
    else if (mr > 0) {
        if (m == mr)       z.x = ((mr & 1) ? -1.0 : 1.0) * is2;
        else if (m == -mr) z.x = is2;
    } else {
        int ma = -mr;
        if (m == mr)      z.y = is2;
        else if (m == ma) z.y = -((ma & 1) ? -1.0 : 1.0) * is2;
    }
    return z;
}
__device__ __forceinline__ double2 cmul(double2 a, double2 b) {
    double2 r; r.x = a.x*b.x - a.y*b.y; r.y = a.x*b.y + a.y*b.x; return r;
}

// warp-per-entry CG init; block 0 also fills K norms + plan tables (TY, G, P)
__global__ void cg_init_kernel() {
    int gw = (blockIdx.x * blockDim.x + threadIdx.x) >> 5;
    int lane = threadIdx.x & 31;

    if (blockIdx.x == 0) {
        for (int t = threadIdx.x; t < 25 + 259 + 552 + 552; t += 256) {
            if (t < 25) {
                int c = t;
                int l = 0;
                while ((l+1)*(l+1) <= c) l++;
                int m = c - l*l - l;
                int am = abs(m);
                double K = sqrt((2.0*l + 1.0) / (4.0 * 3.14159265358979323846) * dfact(l - am) / dfact(l + am));
                g_K[c] = (float)(m == 0 ? K : sqrt(2.0) * K);
            } else if (t < 25 + 259) {
                int item = t - 25;
                int tr = 0;
                while (item >= TY_OFF[tr + 1]) ++tr;
                int local = item - TY_OFF[tr];
                int np = TRIP_NP[tr], nq = TRIP_NQ[tr];
                int q = local / np, p = local % np;
                int l = TRIP_L[tr], nr2 = 2 * l + 1;
                uint32_t cgbase = (uint32_t)(TRIP_CGO[tr] + (p * nq + q) * nr2);
                g_planTY[item] = cgbase | ((uint32_t)(l * l) << 12) | ((uint32_t)nr2 << 17);
            } else if (t < 25 + 259 + 552) {
                int item = t - 25 - 259;
                int tr = 0;
                while (item >= G_OFF[tr + 1]) ++tr;
                int local = item - G_OFF[tr];
                int np = TRIP_NP[tr], nq = TRIP_NQ[tr];
                int v = local / np, p = local % np;
                uint32_t fbase = (uint32_t)(TRIP_FB[tr] + v * nq);
                uint32_t tyb   = (uint32_t)(TY_OFF[tr] + p);
                g_planG[item] = fbase | ((uint32_t)nq << 7) | (tyb << 10) | ((uint32_t)np << 19);
            } else {
                int item = t - 25 - 259 - 552;   // pass-3 unit: (tr, u, p)
                int tr = 0;
                while (item >= G_OFF[tr + 1]) ++tr;
                int local = item - G_OFF[tr];
                int np = TRIP_NP[tr];
                int u = local / np, p = local % np;
                int grp = (tr < 3) ? 0 : (tr < 10) ? 1 : 2;
                int ob  = (grp == 0) ? 0 : (grp == 1) ? 8 : 32;
                int nl  = TRIP_NL[tr];
                uint32_t o  = (uint32_t)(ob + u * np + p);
                uint32_t rb = (uint32_t)(TRIP_RB[tr] + u * 8 * nl + TRIP_KK[tr]);
                uint32_t gb = (uint32_t)(G_OFF[tr] + p);
                uint32_t nlc = (uint32_t)((nl - 1) >> 1);
                uint32_t npc = (uint32_t)((np - 1) >> 1);
                g_planP[item] = o | (rb << 7) | (gb << 18) | (nlc << 28) | (npc << 30);
            }
        }
    }

    if (gw >= 1225) return;
    int idx = gw;
    int t = 0;
    for (t = 0; t < 19; ++t) {
        int sz = (2*TRIP_LO[t]+1) * (2*TRIP_LI[t]+1) * (2*TRIP_L[t]+1);
        if (idx < TRIP_CGO[t] + sz) break;
    }
    int lo = TRIP_LO[t], li = TRIP_LI[t], l = TRIP_L[t];
    int local = idx - TRIP_CGO[t];
    int nq = 2*li + 1, nr = 2*l + 1;
    int p = local / (nq * nr);
    int q = (local / nr) % nq;
    int r = local % nr;
    int n1 = 2*lo + 1;
    int total = n1 * nq * nr;
    double s = 0.0;
    for (int it = lane; it < total; it += 32) {
        int m  = it / (nq * nr);
        int rem = it % (nq * nr);
        int n  = rem / nr;
        int pp = rem % nr;
        double2 u1 = Uent(lo, p, m);
        if (u1.x == 0.0 && u1.y == 0.0) continue;
        double2 u2 = Uent(li, q, n);
        if (u2.x == 0.0 && u2.y == 0.0) continue;
        double2 u3 = Uent(l, r, pp);
        if (u3.x == 0.0 && u3.y == 0.0) continue;
        double w = w3j(lo, li, l, m - lo, n - li, pp - l);
        if (w == 0.0) continue;
        double2 u = cmul(cmul(u1, u2), u3);
        s += (u.x + u.y) * w;
    }
#pragma unroll
    for (int off = 16; off > 0; off >>= 1)
        s += __shfl_down_sync(0xffffffffu, s, off);
    if (lane == 0) g_CG[idx] = (float)s;
}

// ---------------- radial table: one block per node, exact fp32 MLP ----------------
__global__ __launch_bounds__(256)
void table_kernel(const float* __restrict__ W0, const float* __restrict__ W1,
                  const float* __restrict__ W2, const float* __restrict__ W3) {
    __shared__ float ha[HID], hbuf[HID], hb[10];
    const int node = blockIdx.x;
    const int t = threadIdx.x;
    const float d = 0.7f + 2.5f * (float)node / (float)(NT_TAB - 1);

    if (t < 10) {
        float c = 0.7f + (2.5f / 9.0f) * (float)t;
        float tt = (d - c) * 4.5f;
        hb[t] = expf(-tt * tt) * (1.0f / 1.423085244900308f);
    }
    __syncthreads();
    if (t < HID) {
        float s = 0.0f;
#pragma unroll
        for (int b = 0; b < 10; ++b) s += hb[b] * W0[b * HID + t];
        s *= 0.31622776601683794f;
        ha[t] = s / (1.0f + expf(-s));
    }
    __syncthreads();
    if (t < HID) {
        float s = 0.0f;
        for (int k = 0; k < HID; ++k) s += ha[k] * W1[k * HID + t];
        s *= 0.1f;
        hbuf[t] = s / (1.0f + expf(-s));
    }
    __syncthreads();
    if (t < HID) {
        float s = 0.0f;
        for (int k = 0; k < HID; ++k) s += hbuf[k] * W2[k * HID + t];
        s *= 0.1f;
        ha[t] = s / (1.0f + expf(-s));
    }
    __syncthreads();
    for (int o = t; o < NR; o += 256) {
        float s = 0.0f;
        for (int k = 0; k < HID; ++k) s += ha[k] * W3[(size_t)k * NR + o];
        g_T[(size_t)node * NR + o] = 0.1f * s;
    }
}

// ---------------- prep: SH (warp per edge) + zero out ----------------
__global__ __launch_bounds__(256)
void prep_kernel(const float* __restrict__ rel, float* __restrict__ out, int outN) {
    int e = blockIdx.x * 8 + (threadIdx.x >> 5);
    int lane = threadIdx.x & 31;
    int gid = blockIdx.x * 256 + threadIdx.x;
    if (gid < outN) out[gid] = 0.0f;
    if (e >= E_N || lane >= 25) return;

    float vx = rel[e*3+0], vy = rel[e*3+1], vz = rel[e*3+2];
    float r = sqrtf(vx*vx + vy*vy + vz*vz);
    float inv = 1.0f / fmaxf(r, 1e-9f);
    float x = vx * inv, y = vy * inv, z = vz * inv;

    float A[5], B[5];
    A[0] = 1.0f; B[0] = 0.0f;
#pragma unroll
    for (int m = 1; m <= 4; ++m) {
        A[m] = x * A[m-1] - y * B[m-1];
        B[m] = x * B[m-1] + y * A[m-1];
    }
    float p[5][5];
    p[0][0] = 1.0f;
#pragma unroll
    for (int m = 0; m <= 4; ++m) {
        if (m > 0) p[m][m] = -(2.0f * m - 1.0f) * p[m-1][m-1];
        if (m + 1 <= 4) p[m+1][m] = (2.0f * m + 1.0f) * z * p[m][m];
#pragma unroll
        for (int l = m + 2; l <= 4; ++l)
            p[l][m] = ((2.0f*l - 1.0f) * z * p[l-1][m] - (l + m - 1.0f) * p[l-2][m]) / (float)(l - m);
    }
    float val = 0.0f;
    int c = 0;
#pragma unroll
    for (int l = 0; l <= 4; ++l) {
#pragma unroll
        for (int m = -4; m <= 4; ++m) {
            if (m < -l || m > l) continue;
            int am = m < 0 ? -m : m;
            if (c == lane) {
                float gk = g_K[c];
                if (m == 0)      val = gk * p[l][0];
                else if (m > 0)  val = gk * p[l][am] * A[am];
                else             val = gk * p[l][am] * B[am];
            }
            c++;
        }
    }
    g_Yb[(size_t)e * NY + lane] = val;
}

// ---------------- msg4: block per edge; balanced pass-3 units; float4 interp ----------------
__global__ __launch_bounds__(128)
void msg4_kernel(const int* __restrict__ ei, const float* __restrict__ x,
                 const float* __restrict__ dist, float* __restrict__ out) {
    __shared__ float Rs[NR];
    __shared__ float Fs[DIMIN];
    __shared__ float Ys[NY];
    __shared__ float tYs[259];
    __shared__ float Gsm[552];
    __shared__ float smOut[DIMIN];

    const int e = blockIdx.x;
    const int t = threadIdx.x;
    const int src = ei[e];
    const int dst = ei[E_N + e];

    if (t < DIMIN) { smOut[t] = 0.0f; Fs[t] = x[(size_t)src * DIMIN + t]; }
    if (t < NY) Ys[t] = g_Yb[(size_t)e * NY + t];

    // cubic Lagrange interpolation of the radial table (float4)
    {
        float u = (dist[e] - 0.7f) * ((float)(NT_TAB - 1) / 2.5f);
        int i0 = (int)floorf(u);
        i0 = min(max(i0, 1), NT_TAB - 3);
        float tt = u - (float)i0;
        float tm = tt - 1.0f, tp = tt + 1.0f, tm2 = tt - 2.0f;
        float w0 = -tt * tm * tm2 * (1.0f / 6.0f);
        float w1 =  tp * tm * tm2 * 0.5f;
        float w2 = -tp * tt * tm2 * 0.5f;
        float w3 =  tp * tt * tm  * (1.0f / 6.0f);
        const float4* __restrict__ T0 = (const float4*)(g_T + (size_t)(i0 - 1) * NR);
        const float4* __restrict__ T1 = (const float4*)(g_T + (size_t)(i0    ) * NR);
        const float4* __restrict__ T2 = (const float4*)(g_T + (size_t)(i0 + 1) * NR);
        const float4* __restrict__ T3 = (const float4*)(g_T + (size_t)(i0 + 2) * NR);
        float4* __restrict__ Rd = (float4*)Rs;
        for (int i = t; i < NR / 4; i += 128) {
            float4 a = __ldg(T0 + i);
            float4 b = __ldg(T1 + i);
            float4 c = __ldg(T2 + i);
            float4 d4 = __ldg(T3 + i);
            float4 r;
            r.x = w0 * a.x + w1 * b.x + w2 * c.x + w3 * d4.x;
            r.y = w0 * a.y + w1 * b.y + w2 * c.y + w3 * d4.y;
            r.z = w0 * a.z + w1 * b.z + w2 * c.z + w3 * d4.z;
            r.w = w0 * a.w + w1 * b.w + w2 * c.w + w3 * d4.w;
            Rd[i] = r;
        }
    }
    __syncthreads();

    // pass 1: tY
    for (int item = t; item < 259; item += 128) {
        uint32_t plan = __ldg(&g_planTY[item]);
        int cg  = plan & 0xFFF;
        int yb  = (plan >> 12) & 31;
        int nr2 = plan >> 17;
        float s = 0.0f;
        for (int r = 0; r < nr2; ++r)
            s += __ldg(&g_CG[cg + r]) * Ys[yb + r];
        tYs[item] = s;
    }
    __syncthreads();

    // pass 2: G
    for (int item = t; item < 552; item += 128) {
        uint32_t plan = __ldg(&g_planG[item]);
        int fb  = plan & 127;
        int nq  = (plan >> 7) & 7;
        int tyb = (plan >> 10) & 511;
        int np  = (plan >> 19) & 7;
        float s = 0.0f;
        for (int q = 0; q < nq; ++q)
            s += Fs[fb + q] * tYs[tyb + q * np];
        Gsm[item] = s;
    }
    __syncthreads();

    // pass 3: balanced units (o, tr) -> smem accumulate
    for (int g = t; g < 552; g += 128) {
        uint32_t plan = __ldg(&g_planP[g]);
        int o  = plan & 127;
        int rb = (plan >> 7) & 2047;
        int gb = (plan >> 18) & 1023;
        int nl = 1 + 2 * ((plan >> 28) & 3);
        int np = 1 + 2 * ((int)(plan >> 30) & 3);
        const float* rp = Rs + rb;
        const float* gp = Gsm + gb;
        float s = 0.0f;
#pragma unroll
        for (int v = 0; v < 8; ++v) {
            s += rp[0] * gp[0];
            rp += nl; gp += np;
        }
        atomicAdd(&smOut[o], s);
    }
    __syncthreads();

    // flush: norm + global atomic
    if (t < DIMIN) {
        int i = (t < 8) ? 0 : (t < 32) ? 1 : 2;
        const float nse[3] = {24.0f, 56.0f, 72.0f};
        float normi = 3.5449077018110318f * sqrtf(2.0f * i + 1.0f) * rsqrtf(nse[i]);
        atomicAdd(&out[(size_t)dst * DIMIN + t], smOut[t] * normi);
    }
}

// ---------------- launch ----------------
extern "C" void kernel_launch(void* const* d_in, const int* in_sizes, int n_in,
                              void* d_out, int out_size) {
    const int*   ei   = (const int*)  d_in[0];
    const float* x    = (const float*)d_in[1];
    const float* dist = (const float*)d_in[2];
    const float* rel  = (const float*)d_in[3];
    const float* W0   = (const float*)d_in[4];
    const float* W1   = (const float*)d_in[5];
    const float* W2   = (const float*)d_in[6];
    const float* W3   = (const float*)d_in[7];
    float* out = (float*)d_out;

    cg_init_kernel<<<154, 256>>>();                                // 0
    table_kernel<<<NT_TAB, 256>>>(W0, W1, W2, W3);                 // 1
    prep_kernel<<<(E_N + 7) / 8, 256>>>(rel, out, out_size);       // 2
    msg4_kernel<<<E_N, 128>>>(ei, x, dist, out);                   // 3 <- ncu
}

// round 16
// speedup vs baseline: 2.0265x; 1.0647x over previous
#include <cuda_runtime.h>
#include <math.h>
#include <stdint.h>

#define E_N     100000
#define NODES   10000
#define DIMIN   72
#define NR      1216
#define HID     100
#define NY      25
#define NT_TAB  513            // radial table nodes over [0.7, 3.2], h = 2.5/512

// per-edge smem layout (floats)
#define SO_R    0
#define SO_F    1216
#define SO_Y    1288
#define SO_TY   1316
#define SO_G    1576
#define SO_OUT  2128
#define SSTR    2204           // stride between edge 0 and edge 1 regions

// ---------------- scratch (device globals; zero-init) ----------------
__device__ float    g_T [(size_t)NT_TAB * NR];   // radial table f(d_j)
__device__ float    g_Yb[(size_t)E_N * NY];
__device__ float    g_CG[1225];
__device__ float    g_K [25];
__device__ uint32_t g_planTY[259];
__device__ uint32_t g_planG [552];
__device__ uint32_t g_planP [552];

// ---------------- triple metadata (19 (lo,li,l) triples) ----------------
__constant__ int TRIP_LO[19]   = {0,0,0, 1,1,1,1,1,1,1, 2,2,2,2,2,2,2,2,2};
__constant__ int TRIP_LI[19]   = {0,1,2, 0,1,1,1,2,2,2, 0,1,1,1,2,2,2,2,2};
__constant__ int TRIP_L [19]   = {0,1,2, 1,0,1,2,1,2,3, 2,1,2,3,0,1,2,3,4};
__constant__ int TRIP_CGO[19]  = {0,1,10, 35,44,53,80,125,170,245, 350,375,420,495,600,625,700,825,1000};
__constant__ int TRIP_RB[19]   = {0,64,128, 192,256,256,256,448,448,448, 640,704,704,704,896,896,896,896,896};
__constant__ int TRIP_FB[19]   = {0,8,32, 0,8,8,8,32,32,32, 0,8,8,8,32,32,32,32,32};
__constant__ int TRIP_KK[19]   = {0,0,0, 0,0,1,2,0,1,2, 0,0,1,2,0,1,2,3,4};
__constant__ int TRIP_NL[19]   = {1,1,1, 1,3,3,3,3,3,3, 1,3,3,3,5,5,5,5,5};
__constant__ int TRIP_NP[19]   = {1,1,1, 3,3,3,3,3,3,3, 5,5,5,5,5,5,5,5,5};
__constant__ int TRIP_NQ[19]   = {1,3,5, 1,3,3,3,5,5,5, 1,3,3,3,5,5,5,5,5};
__constant__ int TY_OFF[20] = {0,1,4,9, 12,21,30,39,54,69, 84,89,104,119,134,159,184,209,234, 259};
__constant__ int G_OFF [20] = {0,8,16, 24,48,72,96,120,144,168, 192,232,272,312,352,392,432,472,512, 552};

// ---------------- CG math (doubles) ----------------
__device__ __forceinline__ double dfact(int n) {
    const double f[11] = {1.,1.,2.,6.,24.,120.,720.,5040.,40320.,362880.,3628800.};
    return f[n];
}
__device__ double w3j(int j1,int j2,int j3,int m1,int m2,int m3) {
    if (m1 + m2 + m3 != 0) return 0.0;
    if (j3 < abs(j1 - j2) || j3 > j1 + j2) return 0.0;
    if (abs(m1) > j1 || abs(m2) > j2 || abs(m3) > j3) return 0.0;
    double pre = sqrt(dfact(j1+j2-j3)*dfact(j1-j2+j3)*dfact(-j1+j2+j3)/dfact(j1+j2+j3+1)
                 *dfact(j1+m1)*dfact(j1-m1)*dfact(j2+m2)*dfact(j2-m2)*dfact(j3+m3)*dfact(j3-m3));
    int kmin = max(0, max(j2 - j3 - m1, j1 - j3 + m2));
    int kmax = min(j1 + j2 - j3, min(j1 - m1, j2 + m2));
    double s = 0.0;
    for (int k = kmin; k <= kmax; ++k) {
        double den = dfact(k)*dfact(j1+j2-j3-k)*dfact(j1-m1-k)*dfact(j2+m2-k)
                    *dfact(j3-j2+m1+k)*dfact(j3-j1-m2+k);
        s += ((k & 1) ? -1.0 : 1.0) / den;
    }
    int ph = j1 - j2 - m3;
    return ((ph & 1) ? -1.0 : 1.0) * pre * s;
}
__device__ __forceinline__ double2 Uent(int l, int a, int mc) {
    const double is2 = 0.70710678118654752440;
    int mr = a - l, m = mc - l;
    double2 z; z.x = 0.0; z.y = 0.0;
    if (mr == 0) { if (m == 0) z.x = 1.0; }
    else if (mr > 0) {
        if (m == mr)       z.x = ((mr & 1) ? -1.0 : 1.0) * is2;
        else if (m == -mr) z.x = is2;
    } else {
        int ma = -mr;
        if (m == mr)      z.y = is2;
        else if (m == ma) z.y = -((ma & 1) ? -1.0 : 1.0) * is2;
    }
    return z;
}
__device__ __forceinline__ double2 cmul(double2 a, double2 b) {
    double2 r; r.x = a.x*b.x - a.y*b.y; r.y = a.x*b.y + a.y*b.x; return r;
}

// warp-per-entry CG init; block 0 also fills K norms + plan tables (TY, G, P)
__global__ void cg_init_kernel() {
    int gw = (blockIdx.x * blockDim.x + threadIdx.x) >> 5;
    int lane = threadIdx.x & 31;

    if (blockIdx.x == 0) {
        for (int t = threadIdx.x; t < 25 + 259 + 552 + 552; t += 256) {
            if (t < 25) {
                int c = t;
                int l = 0;
                while ((l+1)*(l+1) <= c) l++;
                int m = c - l*l - l;
                int am = abs(m);
                double K = sqrt((2.0*l + 1.0) / (4.0 * 3.14159265358979323846) * dfact(l - am) / dfact(l + am));
                g_K[c] = (float)(m == 0 ? K : sqrt(2.0) * K);
            } else if (t < 25 + 259) {
                int item = t - 25;
                int tr = 0;
                while (item >= TY_OFF[tr + 1]) ++tr;
                int local = item - TY_OFF[tr];
                int np = TRIP_NP[tr], nq = TRIP_NQ[tr];
                int q = local / np, p = local % np;
                int l = TRIP_L[tr], nr2 = 2 * l + 1;
                uint32_t cgbase = (uint32_t)(TRIP_CGO[tr] + (p * nq + q) * nr2);
                g_planTY[item] = cgbase | ((uint32_t)(l * l) << 12) | ((uint32_t)nr2 << 17);
            } else if (t < 25 + 259 + 552) {
                int item = t - 25 - 259;
                int tr = 0;
                while (item >= G_OFF[tr + 1]) ++tr;
                int local = item - G_OFF[tr];
                int np = TRIP_NP[tr], nq = TRIP_NQ[tr];
                int v = local / np, p = local % np;
                uint32_t fbase = (uint32_t)(TRIP_FB[tr] + v * nq);
                uint32_t tyb   = (uint32_t)(TY_OFF[tr] + p);
                g_planG[item] = fbase | ((uint32_t)nq << 7) | (tyb << 10) | ((uint32_t)np << 19);
            } else {
                int item = t - 25 - 259 - 552;   // pass-3 unit: (tr, u, p)
                int tr = 0;
                while (item >= G_OFF[tr + 1]) ++tr;
                int local = item - G_OFF[tr];
                int np = TRIP_NP[tr];
                int u = local / np, p = local % np;
                int grp = (tr < 3) ? 0 : (tr < 10) ? 1 : 2;
                int ob  = (grp == 0) ? 0 : (grp == 1) ? 8 : 32;
                int nl  = TRIP_NL[tr];
                uint32_t o  = (uint32_t)(ob + u * np + p);
                uint32_t rb = (uint32_t)(TRIP_RB[tr] + u * 8 * nl + TRIP_KK[tr]);
                uint32_t gb = (uint32_t)(G_OFF[tr] + p);
                uint32_t nlc = (uint32_t)((nl - 1) >> 1);
                uint32_t npc = (uint32_t)((np - 1) >> 1);
                g_planP[item] = o | (rb << 7) | (gb << 18) | (nlc << 28) | (npc << 30);
            }
        }
    }

    if (gw >= 1225) return;
    int idx = gw;
    int t = 0;
    for (t = 0; t < 19; ++t) {
        int sz = (2*TRIP_LO[t]+1) * (2*TRIP_LI[t]+1) * (2*TRIP_L[t]+1);
        if (idx < TRIP_CGO[t] + sz) break;
    }
    int lo = TRIP_LO[t], li = TRIP_LI[t], l = TRIP_L[t];
    int local = idx - TRIP_CGO[t];
    int nq = 2*li + 1, nr = 2*l + 1;
    int p = local / (nq * nr);
    int q = (local / nr) % nq;
    int r = local % nr;
    int n1 = 2*lo + 1;
    int total = n1 * nq * nr;
    double s = 0.0;
    for (int it = lane; it < total; it += 32) {
        int m  = it / (nq * nr);
        int rem = it % (nq * nr);
        int n  = rem / nr;
        int pp = rem % nr;
        double2 u1 = Uent(lo, p, m);
        if (u1.x == 0.0 && u1.y == 0.0) continue;
        double2 u2 = Uent(li, q, n);
        if (u2.x == 0.0 && u2.y == 0.0) continue;
        double2 u3 = Uent(l, r, pp);
        if (u3.x == 0.0 && u3.y == 0.0) continue;
        double w = w3j(lo, li, l, m - lo, n - li, pp - l);
        if (w == 0.0) continue;
        double2 u = cmul(cmul(u1, u2), u3);
        s += (u.x + u.y) * w;
    }
#pragma unroll
    for (int off = 16; off > 0; off >>= 1)
        s += __shfl_down_sync(0xffffffffu, s, off);
    if (lane == 0) g_CG[idx] = (float)s;
}

// ---------------- radial table: one block per node, exact fp32 MLP ----------------
__global__ __launch_bounds__(256)
void table_kernel(const float* __restrict__ W0, const float* __restrict__ W1,
                  const float* __restrict__ W2, const float* __restrict__ W3) {
    __shared__ float ha[HID], hbuf[HID], hb[10];
    const int node = blockIdx.x;
    const int t = threadIdx.x;
    const float d = 0.7f + 2.5f * (float)node / (float)(NT_TAB - 1);

    if (t < 10) {
        float c = 0.7f + (2.5f / 9.0f) * (float)t;
        float tt = (d - c) * 4.5f;
        hb[t] = expf(-tt * tt) * (1.0f / 1.423085244900308f);
    }
    __syncthreads();
    if (t < HID) {
        float s = 0.0f;
#pragma unroll
        for (int b = 0; b < 10; ++b) s += hb[b] * W0[b * HID + t];
        s *= 0.31622776601683794f;
        ha[t] = s / (1.0f + expf(-s));
    }
    __syncthreads();
    if (t < HID) {
        float s = 0.0f;
        for (int k = 0; k < HID; ++k) s += ha[k] * W1[k * HID + t];
        s *= 0.1f;
        hbuf[t] = s / (1.0f + expf(-s));
    }
    __syncthreads();
    if (t < HID) {
        float s = 0.0f;
        for (int k = 0; k < HID; ++k) s += hbuf[k] * W2[k * HID + t];
        s *= 0.1f;
        ha[t] = s / (1.0f + expf(-s));
    }
    __syncthreads();
    for (int o = t; o < NR; o += 256) {
        float s = 0.0f;
        for (int k = 0; k < HID; ++k) s += ha[k] * W3[(size_t)k * NR + o];
        g_T[(size_t)node * NR + o] = 0.1f * s;
    }
}

// ---------------- prep: SH (warp per edge) + zero out ----------------
__global__ __launch_bounds__(256)
void prep_kernel(const float* __restrict__ rel, float* __restrict__ out, int outN) {
    int e = blockIdx.x * 8 + (threadIdx.x >> 5);
    int lane = threadIdx.x & 31;
    int gid = blockIdx.x * 256 + threadIdx.x;
    if (gid < outN) out[gid] = 0.0f;
    if (e >= E_N || lane >= 25) return;

    float vx = rel[e*3+0], vy = rel[e*3+1], vz = rel[e*3+2];
    float r = sqrtf(vx*vx + vy*vy + vz*vz);
    float inv = 1.0f / fmaxf(r, 1e-9f);
    float x = vx * inv, y = vy * inv, z = vz * inv;

    float A[5], B[5];
    A[0] = 1.0f; B[0] = 0.0f;
#pragma unroll
    for (int m = 1; m <= 4; ++m) {
        A[m] = x * A[m-1] - y * B[m-1];
        B[m] = x * B[m-1] + y * A[m-1];
    }
    float p[5][5];
    p[0][0] = 1.0f;
#pragma unroll
    for (int m = 0; m <= 4; ++m) {
        if (m > 0) p[m][m] = -(2.0f * m - 1.0f) * p[m-1][m-1];
        if (m + 1 <= 4) p[m+1][m] = (2.0f * m + 1.0f) * z * p[m][m];
#pragma unroll
        for (int l = m + 2; l <= 4; ++l)
            p[l][m] = ((2.0f*l - 1.0f) * z * p[l-1][m] - (l + m - 1.0f) * p[l-2][m]) / (float)(l - m);
    }
    float val = 0.0f;
    int c = 0;
#pragma unroll
    for (int l = 0; l <= 4; ++l) {
#pragma unroll
        for (int m = -4; m <= 4; ++m) {
            if (m < -l || m > l) continue;
            int am = m < 0 ? -m : m;
            if (c == lane) {
                float gk = g_K[c];
                if (m == 0)      val = gk * p[l][0];
                else if (m > 0)  val = gk * p[l][am] * A[am];
                else             val = gk * p[l][am] * B[am];
            }
            c++;
        }
    }
    g_Yb[(size_t)e * NY + lane] = val;
}

// ---------------- msg5: TWO edges per block; plan decoded once, applied to both ----------------
__global__ __launch_bounds__(128)
void msg5_kernel(const int* __restrict__ ei, const float* __restrict__ x,
                 const float* __restrict__ dist, float* __restrict__ out) {
    __shared__ float sm[2 * SSTR];

    const int t = threadIdx.x;
    const int e0 = blockIdx.x * 2;
    const int e1 = e0 + 1;
    const int src0 = ei[e0],       src1 = ei[e1];
    const int dst0 = ei[E_N + e0], dst1 = ei[E_N + e1];

    float* __restrict__ S0 = sm;
    float* __restrict__ S1 = sm + SSTR;

    if (t < DIMIN) {
        S0[SO_OUT + t] = 0.0f; S1[SO_OUT + t] = 0.0f;
        S0[SO_F + t] = x[(size_t)src0 * DIMIN + t];
        S1[SO_F + t] = x[(size_t)src1 * DIMIN + t];
    }
    if (t < NY) {
        S0[SO_Y + t] = g_Yb[(size_t)e0 * NY + t];
        S1[SO_Y + t] = g_Yb[(size_t)e1 * NY + t];
    }

    // cubic Lagrange interpolation for both edges (float4)
    {
        float uA = (dist[e0] - 0.7f) * ((float)(NT_TAB - 1) / 2.5f);
        float uB = (dist[e1] - 0.7f) * ((float)(NT_TAB - 1) / 2.5f);
        int iA = min(max((int)floorf(uA), 1), NT_TAB - 3);
        int iB = min(max((int)floorf(uB), 1), NT_TAB - 3);
        float tA = uA - (float)iA, tB = uB - (float)iB;
        float tmA = tA - 1.0f, tpA = tA + 1.0f, t2A = tA - 2.0f;
        float tmB = tB - 1.0f, tpB = tB + 1.0f, t2B = tB - 2.0f;
        float a0 = -tA * tmA * t2A * (1.0f / 6.0f);
        float a1 =  tpA * tmA * t2A * 0.5f;
        float a2 = -tpA * tA * t2A * 0.5f;
        float a3 =  tpA * tA * tmA * (1.0f / 6.0f);
        float b0 = -tB * tmB * t2B * (1.0f / 6.0f);
        float b1 =  tpB * tmB * t2B * 0.5f;
        float b2 = -tpB * tB * t2B * 0.5f;
        float b3 =  tpB * tB * tmB * (1.0f / 6.0f);
        const float4* __restrict__ A0 = (const float4*)(g_T + (size_t)(iA - 1) * NR);
        const float4* __restrict__ A1 = (const float4*)(g_T + (size_t)(iA    ) * NR);
        const float4* __restrict__ A2 = (const float4*)(g_T + (size_t)(iA + 1) * NR);
        const float4* __restrict__ A3 = (const float4*)(g_T + (size_t)(iA + 2) * NR);
        const float4* __restrict__ B0 = (const float4*)(g_T + (size_t)(iB - 1) * NR);
        const float4* __restrict__ B1 = (const float4*)(g_T + (size_t)(iB    ) * NR);
        const float4* __restrict__ B2 = (const float4*)(g_T + (size_t)(iB + 1) * NR);
        const float4* __restrict__ B3 = (const float4*)(g_T + (size_t)(iB + 2) * NR);
        float4* __restrict__ R0 = (float4*)(S0 + SO_R);
        float4* __restrict__ R1 = (float4*)(S1 + SO_R);
        for (int i = t; i < NR / 4; i += 128) {
            float4 p0 = __ldg(A0 + i), p1 = __ldg(A1 + i), p2 = __ldg(A2 + i), p3 = __ldg(A3 + i);
            float4 q0 = __ldg(B0 + i), q1 = __ldg(B1 + i), q2 = __ldg(B2 + i), q3 = __ldg(B3 + i);
            float4 rA, rB;
            rA.x = a0 * p0.x + a1 * p1.x + a2 * p2.x + a3 * p3.x;
            rA.y = a0 * p0.y + a1 * p1.y + a2 * p2.y + a3 * p3.y;
            rA.z = a0 * p0.z + a1 * p1.z + a2 * p2.z + a3 * p3.z;
            rA.w = a0 * p0.w + a1 * p1.w + a2 * p2.w + a3 * p3.w;
            rB.x = b0 * q0.x + b1 * q1.x + b2 * q2.x + b3 * q3.x;
            rB.y = b0 * q0.y + b1 * q1.y + b2 * q2.y + b3 * q3.y;
            rB.z = b0 * q0.z + b1 * q1.z + b2 * q2.z + b3 * q3.z;
            rB.w = b0 * q0.w + b1 * q1.w + b2 * q2.w + b3 * q3.w;
            R0[i] = rA;
            R1[i] = rB;
        }
    }
    __syncthreads();

    // pass 1: tY (decode once, both edges)
    for (int item = t; item < 259; item += 128) {
        uint32_t plan = __ldg(&g_planTY[item]);
        int cg  = plan & 0xFFF;
        int yb  = (plan >> 12) & 31;
        int nr2 = plan >> 17;
        float sA = 0.0f, sB = 0.0f;
        for (int r = 0; r < nr2; ++r) {
            float c = __ldg(&g_CG[cg + r]);
            sA += c * S0[SO_Y + yb + r];
            sB += c * S1[SO_Y + yb + r];
        }
        S0[SO_TY + item] = sA;
        S1[SO_TY + item] = sB;
    }
    __syncthreads();

    // pass 2: G
    for (int item = t; item < 552; item += 128) {
        uint32_t plan = __ldg(&g_planG[item]);
        int fb  = plan & 127;
        int nq  = (plan >> 7) & 7;
        int tyb = (plan >> 10) & 511;
        int np  = (plan >> 19) & 7;
        float sA = 0.0f, sB = 0.0f;
        int ty = SO_TY + tyb;
        for (int q = 0; q < nq; ++q) {
            int fi = SO_F + fb + q;
            sA += S0[fi] * S0[ty];
            sB += S1[fi] * S1[ty];
            ty += np;
        }
        S0[SO_G + item] = sA;
        S1[SO_G + item] = sB;
    }
    __syncthreads();

    // pass 3: balanced units -> smem accumulate (both edges)
    for (int g = t; g < 552; g += 128) {
        uint32_t plan = __ldg(&g_planP[g]);
        int o  = plan & 127;
        int rb = (plan >> 7) & 2047;
        int gb = (plan >> 18) & 1023;
        int nl = 1 + 2 * ((plan >> 28) & 3);
        int np = 1 + 2 * ((int)(plan >> 30) & 3);
        int ri = SO_R + rb, gi = SO_G + gb;
        float sA = 0.0f, sB = 0.0f;
#pragma unroll
        for (int v = 0; v < 8; ++v) {
            sA += S0[ri] * S0[gi];
            sB += S1[ri] * S1[gi];
            ri += nl; gi += np;
        }
        atomicAdd(&S0[SO_OUT + o], sA);
        atomicAdd(&S1[SO_OUT + o], sB);
    }
    __syncthreads();

    // flush: norm + global atomics (both edges)
    if (t < DIMIN) {
        int i = (t < 8) ? 0 : (t < 32) ? 1 : 2;
        const float nse[3] = {24.0f, 56.0f, 72.0f};
        float normi = 3.5449077018110318f * sqrtf(2.0f * i + 1.0f) * rsqrtf(nse[i]);
        atomicAdd(&out[(size_t)dst0 * DIMIN + t], S0[SO_OUT + t] * normi);
        atomicAdd(&out[(size_t)dst1 * DIMIN + t], S1[SO_OUT + t] * normi);
    }
}

// ---------------- launch ----------------
extern "C" void kernel_launch(void* const* d_in, const int* in_sizes, int n_in,
                              void* d_out, int out_size) {
    const int*   ei   = (const int*)  d_in[0];
    const float* x    = (const float*)d_in[1];
    const float* dist = (const float*)d_in[2];
    const float* rel  = (const float*)d_in[3];
    const float* W0   = (const float*)d_in[4];
    const float* W1   = (const float*)d_in[5];
    const float* W2   = (const float*)d_in[6];
    const float* W3   = (const float*)d_in[7];
    float* out = (float*)d_out;

    cg_init_kernel<<<154, 256>>>();                                // 0
    table_kernel<<<NT_TAB, 256>>>(W0, W1, W2, W3);                 // 1
    prep_kernel<<<(E_N + 7) / 8, 256>>>(rel, out, out_size);       // 2
    msg5_kernel<<<E_N / 2, 128>>>(ei, x, dist, out);               // 3 <- ncu
}